// round 16
// baseline (speedup 1.0000x reference)
#include <cuda_runtime.h>
#include <math.h>

#define TN 16000
#define NF 36
#define NB 64
#define NOUT 250
#define NTAPS 257
#define KPHI 569
#define NCH 37
#define TBL 65000

// ---------------- static device scratch ----------------
__device__ float2 d_X[NB * TN];        // scrambled forward FFT of x
__device__ int    d_idx[TBL];          // per-channel gather index (classes C/D/E)
__device__ float  d_wt[TBL];           // per-channel psi weight (incl 1/16000)
__device__ int2   d_sidx[6*4000];      // split units (j=0..2 x parity): two gather indices
__device__ float4 d_swt[6*4000];       // split units: two complex weights
__device__ float  d_phiw[NTAPS];       // time-domain lowpass taps phi(d), d=-128..128
__device__ float2 d_rtA[128];          // W_16000^{-125 i}
__device__ float2 d_rtB[125];          // W_16000^{-i}
__device__ float  d_S1[NB * NCH * NOUT];
__device__ float  d_S1p[NB * 3 * NOUT];  // parity-1 partial sums for j=0..2

// ---------------- complex helpers ----------------
__device__ __forceinline__ float2 cmul(float2 a, float2 b) {
    return make_float2(a.x*b.x - a.y*b.y, a.x*b.y + a.y*b.x);
}
__device__ __forceinline__ float2 cadd(float2 a, float2 b){ return make_float2(a.x+b.x, a.y+b.y); }
__device__ __forceinline__ float2 csub(float2 a, float2 b){ return make_float2(a.x-b.x, a.y-b.y); }

__device__ __forceinline__ int scrampos(int k){
    int e2 = k/1600, r = k - 1600*e2;
    int d2 = r/160;  r -= 160*d2;
    int c2 = r/16;   r -= 16*c2;
    int b2 = r/4,    a2 = r - 4*b2;
    return 4000*a2 + 1000*b2 + 100*c2 + 10*d2 + e2;
}
__device__ __forceinline__ float psiwt(int k, float xi, float sg){
    float f = (k < 8000) ? (float)k/16000.0f : (float)(k - 16000)/16000.0f;
    float u = (f - xi) / sg;
    return (u*u < 50.0f) ? __expf(-0.5f*u*u)/16000.0f : 0.0f;
}

// ---------------- ONE prep kernel ----------------
__global__ void prep_all2() {
    int row = blockIdx.y;
    int q = blockIdx.x * blockDim.x + threadIdx.x;
    const float rr  = exp2f(1.0f/6.0f);
    const float fac = (rr - 1.0f) / (rr + 1.0f);
    if (row < NF) {
        int j = row;
        if (j < 3) return;
        int cls, NJ, off;
        if      (j < 10){ cls=2; NJ=4000; off = (j-3)*4000; }
        else if (j < 21){ cls=3; NJ=2000; off = 28000 + (j-10)*2000; }
        else            { cls=4; NJ=1000; off = 50000 + (j-21)*1000; }
        if (q >= NJ) return;
        int kq;
        if      (cls == 2) { int b=q/1000, c=(q/100)%10, d=(q/10)%10, e=q%10; kq = b + 4*c + 40*d + 400*e; }
        else if (cls == 3) { int a=q/1000, c=(q/100)%10, d=(q/10)%10, e=q%10; kq = a + 2*c + 20*d + 200*e; }
        else               { int c=q/100, d=(q/10)%10, e=q%10; kq = c + 10*d + 100*e; }
        float xi = 0.35f * exp2f(-(float)j/6.0f);
        int k_lo = (int)(xi * 16000.0f) - NJ/2;
        if (k_lo < 0) k_lo = 0;
        int k = k_lo + kq;
        d_idx[off+q] = scrampos(k);
        d_wt[off+q]  = psiwt(k, xi, xi*fac);
    } else if (row < NF + 6) {
        int u = row - NF;
        int j = u >> 1, pi = u & 1;
        if (q >= 4000) return;
        int b=q/1000, c=(q/100)%10, d=(q/10)%10, e=q%10;
        int kq = b + 4*c + 40*d + 400*e;
        float xi = 0.35f * exp2f(-(float)j/6.0f);
        int k_lo = (int)(xi * 16000.0f) - 4000;
        if (k_lo < 0) k_lo = 0;
        int k1 = k_lo + kq, k2 = k_lo + kq + 4000;
        float sg = xi*fac;
        float p1 = psiwt(k1, xi, sg);
        float p2 = psiwt(k2, xi, sg);
        float2 ph = make_float2(1.f, 0.f);
        if (pi) { float s, cx; sincospif((float)kq/4000.0f, &s, &cx); ph = make_float2(cx, s); }
        float sgn = pi ? -1.f : 1.f;
        d_sidx[u*4000+q] = make_int2(scrampos(k1), scrampos(k2));
        d_swt[u*4000+q]  = make_float4(p1*ph.x, p1*ph.y, sgn*p2*ph.x, sgn*p2*ph.y);
    } else if (row == NF + 6) {
        int tap  = blockIdx.x*8 + (threadIdx.x >> 5);
        int lane = threadIdx.x & 31;
        if (tap >= NTAPS) return;
        int d = tap - 128;
        const float sp = 0.35f / 64.0f;
        float acc = 0.f;
        for (int k = 1 + lane; k <= KPHI; k += 32) {
            float f = (float)k / 16000.0f;
            float g = __expf(-f*f / (2.0f*sp*sp));
            acc += g * cospif(2.0f * (float)(k*d) / 16000.0f);
        }
        for (int o = 16; o; o >>= 1) acc += __shfl_down_sync(0xffffffffu, acc, o);
        if (lane == 0) d_phiw[tap] = (1.0f + 2.0f*acc) / 16000.0f;
    } else {
        if (q < 128) { float s, c; sincospif(-(float)q/64.0f, &s, &c); d_rtA[q] = make_float2(c, s); }
        else if (q < 253) { int t = q-128; float s, c; sincospif(-(float)t/8000.0f, &s, &c); d_rtB[t] = make_float2(c, s); }
    }
}

// ---------------- small DFTs ----------------
template<int SIGN>
__device__ __forceinline__ void dft4(float2&z0,float2&z1,float2&z2,float2&z3){
    float2 t0=cadd(z0,z2), t1=csub(z0,z2), t2=cadd(z1,z3), t3=csub(z1,z3);
    const float s = (float)SIGN;
    z0 = cadd(t0,t2);
    z2 = csub(t0,t2);
    z1 = make_float2(t1.x - s*t3.y, t1.y + s*t3.x);
    z3 = make_float2(t1.x + s*t3.y, t1.y - s*t3.x);
}

template<int SIGN>
__device__ __forceinline__ void dft5(float2&z0,float2&z1,float2&z2,float2&z3,float2&z4){
    const float K1 =  0.309016994374947424f;
    const float K2 = -0.809016994374947424f;
    const float S1 =  0.951056516295153572f;
    const float S2 =  0.587785252292473129f;
    float2 t1=cadd(z1,z4), t2=cadd(z2,z3), t3=csub(z1,z4), t4=csub(z2,z3);
    float2 a = z0;
    float2 sum = cadd(a, cadd(t1,t2));
    float2 r1 = make_float2(a.x + K1*t1.x + K2*t2.x, a.y + K1*t1.y + K2*t2.y);
    float2 r2 = make_float2(a.x + K2*t1.x + K1*t2.x, a.y + K2*t1.y + K1*t2.y);
    float2 q1 = make_float2(S1*t3.x + S2*t4.x, S1*t3.y + S2*t4.y);
    float2 q2 = make_float2(S2*t3.x - S1*t4.x, S2*t3.y - S1*t4.y);
    const float s = (float)SIGN;
    z0 = sum;
    z1 = make_float2(r1.x - s*q1.y, r1.y + s*q1.x);
    z4 = make_float2(r1.x + s*q1.y, r1.y - s*q1.x);
    z2 = make_float2(r2.x - s*q2.y, r2.y + s*q2.x);
    z3 = make_float2(r2.x + s*q2.y, r2.y - s*q2.x);
}

__device__ __forceinline__ float2 twb(int x, const float2* rtA, const float2* rtB){
    int a = x / 125;
    return cmul(rtA[a], rtB[x - a*125]);
}

// forward radix-10 stage, block-local (cnt=400, 512 thr)
template<int M, int CC>
__device__ void stage10fg(float2* buf, const float2* rtA, const float2* rtB){
    const float c1x=0.809016994374947424f, c1y=0.587785252292473129f;
    const float c2x=0.309016994374947424f, c2y=0.951056516295153572f;
    const float2 w10_1 = make_float2( c1x, -c1y);
    const float2 w10_2 = make_float2( c2x, -c2y);
    const float2 w10_3 = make_float2(-c2x, -c2y);
    const float2 w10_4 = make_float2(-c1x, -c1y);
    for (int idx = threadIdx.x; idx < 400; idx += 512) {
        int blk = idx / M;
        int p   = idx - blk*M;
        int o   = blk*(10*M) + p;
        float2 z[10];
        #pragma unroll
        for (int i=0;i<10;i++) z[i] = buf[o + M*i];
        float2 v = twb(CC*p, rtA, rtB);
        float2 b  = cmul(v,v);
        float2 b2 = cmul(b,b);
        float2 b3 = cmul(b2,b);
        float2 b4 = cmul(b2,b2);
        float2 m1 = cmul(w10_1, v);
        float2 m2 = cmul(w10_2, v);
        float2 m3 = cmul(w10_3, v);
        float2 m4 = cmul(w10_4, v);
        float2 e0=cadd(z[0],z[5]), e1=cadd(z[1],z[6]), e2=cadd(z[2],z[7]), e3=cadd(z[3],z[8]), e4=cadd(z[4],z[9]);
        float2 q0=cmul(csub(z[0],z[5]), v ), q1=cmul(csub(z[1],z[6]), m1),
               q2=cmul(csub(z[2],z[7]), m2), q3=cmul(csub(z[3],z[8]), m3),
               q4=cmul(csub(z[4],z[9]), m4);
        dft5<-1>(e0,e1,e2,e3,e4);
        dft5<-1>(q0,q1,q2,q3,q4);
        z[0]=e0;          z[1]=q0;
        z[2]=cmul(e1,b);  z[3]=cmul(q1,b);
        z[4]=cmul(e2,b2); z[5]=cmul(q2,b2);
        z[6]=cmul(e3,b3); z[7]=cmul(q3,b3);
        z[8]=cmul(e4,b4); z[9]=cmul(q4,b4);
        #pragma unroll
        for (int i=0;i<10;i++) buf[o + M*i] = z[i];
    }
    __syncthreads();
}

// ================= merged forward: radix-4 component from global + local [4,10,10,10] =================
// grid (4, NB): CTA (s,b) computes sub-block s (k mod 4 == s), 4000 points, writes d_X[b*TN + 4000s ..)
__global__ __launch_bounds__(512) void k_fwd2(const float* __restrict__ x){
    extern __shared__ __align__(16) unsigned char sm[];
    float2* buf = (float2*)sm;                       // 4000 complex
    __shared__ float2 rtA[128]; __shared__ float2 rtB[125];
    for (int i = threadIdx.x; i < 128; i += 512) rtA[i] = d_rtA[i];
    for (int i = threadIdx.x; i < 125; i += 512) rtB[i] = d_rtB[i];
    int s = blockIdx.x, b = blockIdx.y;
    const float* xb = x + b*TN;
    __syncthreads();
    // level-1 radix-4 component s (x real), twiddle W^{-s p}
    for (int p = threadIdx.x; p < 4000; p += 512) {
        float x0=xb[p], x1=xb[p+4000], x2=xb[p+8000], x3=xb[p+12000];
        float2 comp;
        if      (s==0) comp = make_float2(x0+x1+x2+x3, 0.f);
        else if (s==1) comp = make_float2(x0-x2, -(x1-x3));
        else if (s==2) comp = make_float2(x0-x1+x2-x3, 0.f);
        else           comp = make_float2(x0-x2,  (x1-x3));
        if (s) comp = cmul(comp, twb(s*p, rtA, rtB));
        buf[p] = comp;
    }
    __syncthreads();
    // level-2 radix-4, M=1000, twiddle W_16000^{-4 p s2}
    for (int p = threadIdx.x; p < 1000; p += 512) {
        float2 z0=buf[p], z1=buf[p+1000], z2=buf[p+2000], z3=buf[p+3000];
        dft4<-1>(z0,z1,z2,z3);
        float2 w1 = twb(4*p, rtA, rtB);
        float2 w2 = cmul(w1,w1), w3 = cmul(w2,w1);
        z1=cmul(z1,w1); z2=cmul(z2,w2); z3=cmul(z3,w3);
        buf[p]=z0; buf[p+1000]=z1; buf[p+2000]=z2; buf[p+3000]=z3;
    }
    __syncthreads();
    stage10fg<100,16>(buf, rtA, rtB);
    stage10fg<10,160>(buf, rtA, rtB);
    // final radix-10 M=1, no twiddle, store natural
    const float c1x=0.809016994374947424f, c1y=0.587785252292473129f;
    const float c2x=0.309016994374947424f, c2y=0.951056516295153572f;
    const float2 w1 = make_float2( c1x, -c1y);
    const float2 w2 = make_float2( c2x, -c2y);
    const float2 w3 = make_float2(-c2x, -c2y);
    const float2 w4 = make_float2(-c1x, -c1y);
    float2* Xo = d_X + b*TN + s*4000;
    for (int blk = threadIdx.x; blk < 400; blk += 512) {
        int o = 10*blk;
        float2 z[10];
        #pragma unroll
        for (int i=0;i<10;i++) z[i] = buf[o+i];
        float2 e0=cadd(z[0],z[5]), e1=cadd(z[1],z[6]), e2=cadd(z[2],z[7]), e3=cadd(z[3],z[8]), e4=cadd(z[4],z[9]);
        float2 q0=csub(z[0],z[5]),           q1=cmul(csub(z[1],z[6]), w1),
               q2=cmul(csub(z[2],z[7]), w2), q3=cmul(csub(z[3],z[8]), w3),
               q4=cmul(csub(z[4],z[9]), w4);
        dft5<-1>(e0,e1,e2,e3,e4);
        dft5<-1>(q0,q1,q2,q3,q4);
        float4* X4 = (float4*)(Xo + o);
        X4[0] = make_float4(e0.x,e0.y,q0.x,q0.y);
        X4[1] = make_float4(e1.x,e1.y,q1.x,q1.y);
        X4[2] = make_float4(e2.x,e2.y,q2.x,q2.y);
        X4[3] = make_float4(e3.x,e3.y,q3.x,q3.y);
        X4[4] = make_float4(e4.x,e4.y,q4.x,q4.y);
    }
}

// ================= S0: smem-windowed warp-per-output smoothing =================
// grid (8, NB): CTA g covers outputs [32g, 32g+32); window = 2241 samples, no inner modulo
__global__ __launch_bounds__(256) void k_s0(const float* __restrict__ x){
    __shared__ float sphi[NTAPS];
    __shared__ float sx[2304];
    int g = blockIdx.x, b = blockIdx.y;
    const float* xb = x + b*TN;
    int base = 64*32*g - 128;
    for (int i = threadIdx.x; i < NTAPS; i += 256) sphi[i] = d_phiw[i];
    for (int t = threadIdx.x; t < 2304; t += 256) {
        int id = base + t;
        if (id < 0)   id += TN;
        if (id >= TN) id -= TN;
        sx[t] = xb[id];
    }
    __syncthreads();
    int w = threadIdx.x >> 5, l = threadIdx.x & 31;
    for (int m0 = g*32 + w; m0 < NOUT && m0 < g*32 + 32; m0 += 8) {
        int offb = 64*(m0 - g*32) + 256;
        float acc = 0.f;
        #pragma unroll
        for (int it = 0; it < 9; ++it) {
            int tl = l + 32*it;
            if (tl <= 256) acc += sphi[tl] * sx[offb - tl];
        }
        #pragma unroll
        for (int o = 16; o; o >>= 1) acc += __shfl_down_sync(0xffffffffu, acc, o);
        if (l == 0) d_S1[(b*NCH)*NOUT + m0] = acc;
    }
}

// ================= inverse pieces (generalized over sub-unit tid/THRL) =================

template<int THRL>
__device__ void s10_load_g(int t, float2* buf, const float2* __restrict__ Xb,
                           const int* __restrict__ idx, const float* __restrict__ wt, int cnt10){
    const float c1x=0.809016994374947424f, c1y=0.587785252292473129f;
    const float c2x=0.309016994374947424f, c2y=0.951056516295153572f;
    const float2 w1 = make_float2( c1x,  c1y);
    const float2 w2 = make_float2( c2x,  c2y);
    const float2 w3 = make_float2(-c2x,  c2y);
    const float2 w4 = make_float2(-c1x,  c1y);
    for (int blk = t; blk < cnt10; blk += THRL) {
        int o = 10*blk;
        float2 z[10];
        #pragma unroll
        for (int i=0;i<10;i++){
            float2 v = Xb[idx[o+i]];
            float  w = wt[o+i];
            z[i] = make_float2(v.x*w, v.y*w);
        }
        float2 E0=z[0], E1=z[2], E2=z[4], E3=z[6], E4=z[8];
        float2 O0=z[1], O1=z[3], O2=z[5], O3=z[7], O4=z[9];
        dft5<1>(E0,E1,E2,E3,E4);
        dft5<1>(O0,O1,O2,O3,O4);
        O1=cmul(O1,w1); O2=cmul(O2,w2); O3=cmul(O3,w3); O4=cmul(O4,w4);
        buf[o  ]=cadd(E0,O0); buf[o+5]=csub(E0,O0);
        buf[o+1]=cadd(E1,O1); buf[o+6]=csub(E1,O1);
        buf[o+2]=cadd(E2,O2); buf[o+7]=csub(E2,O2);
        buf[o+3]=cadd(E3,O3); buf[o+8]=csub(E3,O3);
        buf[o+4]=cadd(E4,O4); buf[o+9]=csub(E4,O4);
    }
    __syncthreads();
}

__device__ void s10_load_dual(float2* buf, const float2* __restrict__ Xb,
                              const int2* __restrict__ sidx, const float4* __restrict__ swt){
    const float c1x=0.809016994374947424f, c1y=0.587785252292473129f;
    const float c2x=0.309016994374947424f, c2y=0.951056516295153572f;
    const float2 w1 = make_float2( c1x,  c1y);
    const float2 w2 = make_float2( c2x,  c2y);
    const float2 w3 = make_float2(-c2x,  c2y);
    const float2 w4 = make_float2(-c1x,  c1y);
    for (int blk = threadIdx.x; blk < 400; blk += 512) {
        int o = 10*blk;
        float2 z[10];
        #pragma unroll
        for (int i=0;i<10;i++){
            int2   ii = sidx[o+i];
            float4 ww = swt[o+i];
            float2 v1 = Xb[ii.x];
            float2 v2 = Xb[ii.y];
            z[i] = cadd(cmul(v1, make_float2(ww.x, ww.y)), cmul(v2, make_float2(ww.z, ww.w)));
        }
        float2 E0=z[0], E1=z[2], E2=z[4], E3=z[6], E4=z[8];
        float2 O0=z[1], O1=z[3], O2=z[5], O3=z[7], O4=z[9];
        dft5<1>(E0,E1,E2,E3,E4);
        dft5<1>(O0,O1,O2,O3,O4);
        O1=cmul(O1,w1); O2=cmul(O2,w2); O3=cmul(O3,w3); O4=cmul(O4,w4);
        buf[o  ]=cadd(E0,O0); buf[o+5]=csub(E0,O0);
        buf[o+1]=cadd(E1,O1); buf[o+6]=csub(E1,O1);
        buf[o+2]=cadd(E2,O2); buf[o+7]=csub(E2,O2);
        buf[o+3]=cadd(E3,O3); buf[o+8]=csub(E3,O3);
        buf[o+4]=cadd(E4,O4); buf[o+9]=csub(E4,O4);
    }
    __syncthreads();
}

template<int M, int CC, int THRL, bool ABS>
__device__ void s10i_g(int t, float2* buf, float* U, int cnt, const float2* rtA, const float2* rtB){
    const float c1x=0.809016994374947424f, c1y=0.587785252292473129f;
    const float c2x=0.309016994374947424f, c2y=0.951056516295153572f;
    const float2 w10_1 = make_float2( c1x,  c1y);
    const float2 w10_2 = make_float2( c2x,  c2y);
    const float2 w10_3 = make_float2(-c2x,  c2y);
    const float2 w10_4 = make_float2(-c1x,  c1y);
    for (int idx = t; idx < cnt; idx += THRL) {
        int blk = idx / M;
        int p   = idx - blk*M;
        int o   = blk*(10*M) + p;
        float2 z[10];
        #pragma unroll
        for (int i=0;i<10;i++) z[i] = buf[o + M*i];
        float2 v = twb(CC*p, rtA, rtB);
        v.y = -v.y;
        float2 b  = cmul(v,v);
        float2 b2 = cmul(b,b);
        float2 b3 = cmul(b2,b);
        float2 b4 = cmul(b2,b2);
        float2 m1 = cmul(w10_1, v);
        float2 m2 = cmul(w10_2, v);
        float2 m3 = cmul(w10_3, v);
        float2 m4 = cmul(w10_4, v);
        float2 E0=z[0], E1=cmul(z[2],b), E2=cmul(z[4],b2), E3=cmul(z[6],b3), E4=cmul(z[8],b4);
        float2 O0=z[1], O1=cmul(z[3],b), O2=cmul(z[5],b2), O3=cmul(z[7],b3), O4=cmul(z[9],b4);
        dft5<1>(E0,E1,E2,E3,E4);
        dft5<1>(O0,O1,O2,O3,O4);
        O0=cmul(O0,v ); O1=cmul(O1,m1); O2=cmul(O2,m2); O3=cmul(O3,m3); O4=cmul(O4,m4);
        float2 y[10];
        y[0]=cadd(E0,O0); y[5]=csub(E0,O0);
        y[1]=cadd(E1,O1); y[6]=csub(E1,O1);
        y[2]=cadd(E2,O2); y[7]=csub(E2,O2);
        y[3]=cadd(E3,O3); y[8]=csub(E3,O3);
        y[4]=cadd(E4,O4); y[9]=csub(E4,O4);
        if (ABS) {
            #pragma unroll
            for (int i=0;i<10;i++) U[o + M*i] = sqrtf(y[i].x*y[i].x + y[i].y*y[i].y);
        } else {
            #pragma unroll
            for (int i=0;i<10;i++) buf[o + M*i] = y[i];
        }
    }
    __syncthreads();
}

template<int THRL, bool ABS>
__device__ void s4i_g(int t, float2* buf, float* U, int cnt, const float2* rtA, const float2* rtB){
    for (int idx = t; idx < cnt; idx += THRL) {
        int blk = idx / 1000;
        int p   = idx - blk*1000;
        int o   = blk*4000 + p;
        float2 z0=buf[o], z1=buf[o+1000], z2=buf[o+2000], z3=buf[o+3000];
        float2 w1 = twb(4*p, rtA, rtB); w1.y = -w1.y;
        float2 w2 = cmul(w1,w1), w3 = cmul(w2,w1);
        z1=cmul(z1,w1); z2=cmul(z2,w2); z3=cmul(z3,w3);
        dft4<1>(z0,z1,z2,z3);
        if (ABS) {
            U[o]      = sqrtf(z0.x*z0.x + z0.y*z0.y);
            U[o+1000] = sqrtf(z1.x*z1.x + z1.y*z1.y);
            U[o+2000] = sqrtf(z2.x*z2.x + z2.y*z2.y);
            U[o+3000] = sqrtf(z3.x*z3.x + z3.y*z3.y);
        } else {
            buf[o]=z0; buf[o+1000]=z1; buf[o+2000]=z2; buf[o+3000]=z3;
        }
    }
    __syncthreads();
}

template<int THRL, int M2, int DD>
__device__ void s2i_abs_g(int t, float2* buf, float* U, const float2* rtA, const float2* rtB){
    for (int p = t; p < M2; p += THRL) {
        float2 a = buf[p];
        float2 w = twb(DD*p, rtA, rtB); w.y = -w.y;
        float2 bb = cmul(buf[p+M2], w);
        float2 y0 = cadd(a,bb), y1 = csub(a,bb);
        U[p]    = sqrtf(y0.x*y0.x + y0.y*y0.y);
        U[p+M2] = sqrtf(y1.x*y1.x + y1.y*y1.y);
    }
    __syncthreads();
}

template<int THRL>
__device__ void init_tables(float2* rtA, float2* rtB, float* sphi){
    for (int i = threadIdx.x; i < 128; i += THRL) rtA[i] = d_rtA[i];
    for (int i = threadIdx.x; i < 125; i += THRL) rtB[i] = d_rtB[i];
    for (int i = threadIdx.x; i < NTAPS; i += THRL) sphi[i] = d_phiw[i];
}

template<int NJ, int DEC, int THRL>
__device__ void smooth_dec_g(int t, const float* __restrict__ S, const float* __restrict__ sphi, float* dst){
    const int T = 128 / DEC;
    const int ITER = (2*T + 1 + 31) / 32;
    int w = t >> 5, l = t & 31;
    for (int m0 = w; m0 < NOUT; m0 += THRL/32) {
        int tau = (64/DEC) * m0;
        float acc = 0.f;
        #pragma unroll
        for (int it = 0; it < ITER; ++it) {
            int tl = l + 32*it;
            if (tl <= 2*T) {
                int i = tl - T;
                int id = tau - i;
                if (id >= NJ) id -= NJ;
                if (id < 0)   id += NJ;
                acc += sphi[DEC*i + 128] * S[id];
            }
        }
        #pragma unroll
        for (int o = 16; o; o >>= 1) acc += __shfl_down_sync(0xffffffffu, acc, o);
        if (l == 0) dst[m0] = acc * (float)DEC;
    }
}

template<int PI>
__device__ void smooth_split(const float* __restrict__ S, const float* __restrict__ sphi, float* dst){
    int w = threadIdx.x >> 5, l = threadIdx.x & 31;
    for (int m0 = w; m0 < NOUT; m0 += 16) {
        int tau = 16*m0 - PI;
        float acc = 0.f;
        #pragma unroll
        for (int it = 0; it < 3; ++it) {
            int t = l + 32*it;
            if (t <= 64 - PI) {
                int i = t - 32;
                int id = tau - i;
                if (id >= 4000) id -= 4000;
                if (id < 0)     id += 4000;
                acc += sphi[4*i + 2*PI + 128] * S[id];
            }
        }
        #pragma unroll
        for (int o = 16; o; o >>= 1) acc += __shfl_down_sync(0xffffffffu, acc, o);
        if (l == 0) dst[m0] = 2.0f * acc;
    }
}

// ---------------- unified band kernel: 23 CTAs per batch ----------------
__global__ __launch_bounds__(512, 3) void k_band_all(){
    extern __shared__ __align__(16) unsigned char sm[];
    __shared__ float2 rtA[128]; __shared__ float2 rtB[125]; __shared__ float sphi[NTAPS];
    int u = blockIdx.x, b = blockIdx.y;
    int tid = threadIdx.x;
    init_tables<512>(rtA, rtB, sphi);
    __syncthreads();
    const float2* Xb = d_X + b*TN;
    if (u < 6) {
        float2* buf = (float2*)sm;
        float*  U   = (float*)(sm + 4000*sizeof(float2));
        int j = u >> 1, pi = u & 1;
        s10_load_dual(buf, Xb, d_sidx + u*4000, d_swt + u*4000);
        s10i_g<10,160,512,false>(tid, buf, U, 400, rtA, rtB);
        s10i_g<100,16,512,false>(tid, buf, U, 400, rtA, rtB);
        s4i_g<512,true>(tid, buf, U, 1000, rtA, rtB);
        if (pi == 0) smooth_split<0>(U, sphi, &d_S1[(b*NCH + 1 + j)*NOUT]);
        else         smooth_split<1>(U, sphi, &d_S1p[(b*3 + j)*NOUT]);
    } else if (u < 13) {
        float2* buf = (float2*)sm;
        float*  U   = (float*)(sm + 4000*sizeof(float2));
        int jc = u - 6;
        s10_load_g<512>(tid, buf, Xb, d_idx + jc*4000, d_wt + jc*4000, 400);
        s10i_g<10,160,512,false>(tid, buf, U, 400, rtA, rtB);
        s10i_g<100,16,512,false>(tid, buf, U, 400, rtA, rtB);
        s4i_g<512,true>(tid, buf, U, 1000, rtA, rtB);
        smooth_dec_g<4000,4,512>(tid, U, sphi, &d_S1[(b*NCH + 1 + 3 + jc)*NOUT]);
    } else if (u < 19) {
        int sub = tid >> 8, t = tid & 255;
        int jc = (u - 13)*2 + sub; if (jc > 10) jc = 10;
        float2* buf = (float2*)(sm + sub*24000);
        float*  U   = (float*)(sm + sub*24000 + 2000*sizeof(float2));
        s10_load_g<256>(t, buf, Xb, d_idx + 28000 + jc*2000, d_wt + 28000 + jc*2000, 200);
        s10i_g<10,160,256,false>(t, buf, U, 200, rtA, rtB);
        s10i_g<100,16,256,false>(t, buf, U, 200, rtA, rtB);
        s2i_abs_g<256,1000,8>(t, buf, U, rtA, rtB);
        smooth_dec_g<2000,8,256>(t, U, sphi, &d_S1[(b*NCH + 1 + 10 + jc)*NOUT]);
    } else {
        int sub = tid >> 7, t = tid & 127;
        int jc = (u - 19)*4 + sub; if (jc > 14) jc = 14;
        float2* buf = (float2*)(sm + sub*12000);
        float*  U   = (float*)(sm + sub*12000 + 1000*sizeof(float2));
        s10_load_g<128>(t, buf, Xb, d_idx + 50000 + jc*1000, d_wt + 50000 + jc*1000, 100);
        s10i_g<10,160,128,false>(t, buf, U, 100, rtA, rtB);
        s10i_g<100,16,128,true>(t, buf, U, 100, rtA, rtB);
        smooth_dec_g<1000,16,128>(t, U, sphi, &d_S1[(b*NCH + 1 + 21 + jc)*NOUT]);
    }
}

// ---------------- kernel 3: channel-group means (+ parity-1 partials for j=0..2) ----------------
__global__ void k_reduce(float* __restrict__ out){
    int i = blockIdx.x * blockDim.x + threadIdx.x;
    if (i >= NB*3*NOUT) return;
    int m0 = i % NOUT;
    int g  = (i / NOUT) % 3;
    int b  = i / (3*NOUT);
    int c0 = (g==0) ? 0 : (g==1 ? 12 : 24);
    int nc = (g==2) ? 13 : 12;
    float acc = 0.f;
    for (int c = 0; c < nc; ++c) acc += d_S1[(b*NCH + c0 + c)*NOUT + m0];
    if (g == 0) {
        for (int j = 0; j < 3; ++j) acc += d_S1p[(b*3 + j)*NOUT + m0];
    }
    out[i] = acc / (float)nc;
}

// ---------------- launch ----------------
extern "C" void kernel_launch(void* const* d_in, const int* in_sizes, int n_in,
                              void* d_out, int out_size) {
    (void)in_sizes; (void)n_in; (void)out_size;
    const float* x = (const float*)d_in[0];
    float* out = (float*)d_out;
    const int smBand = 48000;
    const int smFW   = 32000;
    cudaFuncSetAttribute(k_band_all, cudaFuncAttributeMaxDynamicSharedMemorySize, smBand);
    cudaFuncSetAttribute(k_fwd2,     cudaFuncAttributeMaxDynamicSharedMemorySize, smFW);
    prep_all2<<<dim3(33, NF + 8), 256>>>();
    k_fwd2<<<dim3(4, NB), 512, smFW>>>(x);
    k_s0<<<dim3(8, NB), 256>>>(x);
    k_band_all<<<dim3(23, NB), 512, smBand>>>();
    k_reduce<<<(NB*3*NOUT + 511)/512, 512>>>(out);
}